// round 2
// baseline (speedup 1.0000x reference)
#include <cuda_runtime.h>
#include <cstdint>

#define NN 100000
#define EE 1600000
#define DD 32
#define CUT_K 320000   // int(1600000 * 0.2)
#define EPS 1e-12f

// ---------------- scratch (static device globals; no allocation) ----------------
__device__ float     g_Y1[NN * DD];
__device__ float     g_Y2[NN * DD];
__device__ float     g_cos[EE];
__device__ float     g_rn[NN];      // 1 / max(||row||, eps)
__device__ float     g_norm[NN];    // clip(deg,1)^-0.5
__device__ int       g_deg[NN];
__device__ unsigned  g_hist[256];
__device__ unsigned  g_prefix;      // radix-select prefix / final threshold key
__device__ unsigned  g_kremain;     // remaining rank within candidates; final = #equal-to-T to drop
__device__ unsigned  g_ticket;      // tie-break ticket counter

// monotone float -> uint key (ascending float order == ascending unsigned order)
__device__ __forceinline__ unsigned fkey(float f) {
    unsigned u = __float_as_uint(f);
    return (u & 0x80000000u) ? ~u : (u | 0x80000000u);
}

// ---------------- kernels ----------------

__global__ void k_zero_deg() {
    int i = blockIdx.x * blockDim.x + threadIdx.x;
    if (i < NN) g_deg[i] = 0;
}

__global__ void k_deg(const int* __restrict__ dst) {
    int e = blockIdx.x * blockDim.x + threadIdx.x;
    if (e < EE) atomicAdd(&g_deg[dst[e]], 1);
}

__global__ void k_norm() {
    int i = blockIdx.x * blockDim.x + threadIdx.x;
    if (i < NN) {
        int d = g_deg[i];
        if (d < 1) d = 1;
        g_norm[i] = 1.0f / sqrtf((float)d);
    }
}

__global__ void k_zeroY(float4* __restrict__ Y4) {
    int i = blockIdx.x * blockDim.x + threadIdx.x;
    if (i < NN * (DD / 4)) Y4[i] = make_float4(0.f, 0.f, 0.f, 0.f);
}

// 8 lanes per node: inverse L2 norm of each row
__global__ void k_rn(const float4* __restrict__ X4) {
    int gid  = blockIdx.x * blockDim.x + threadIdx.x;
    int node = gid >> 3;
    int sub  = gid & 7;
    if (node >= NN) return;
    float4 v = X4[node * 8 + sub];
    float s = v.x * v.x + v.y * v.y + v.z * v.z + v.w * v.w;
    s += __shfl_xor_sync(0xffffffffu, s, 1);
    s += __shfl_xor_sync(0xffffffffu, s, 2);
    s += __shfl_xor_sync(0xffffffffu, s, 4);
    if (sub == 0) g_rn[node] = 1.0f / fmaxf(sqrtf(s), EPS);
}

// 8 lanes per edge: cosine similarity
__global__ void k_cos(const float4* __restrict__ X4,
                      const int* __restrict__ src, const int* __restrict__ dst) {
    int gid = blockIdx.x * blockDim.x + threadIdx.x;
    int e   = gid >> 3;
    int sub = gid & 7;
    if (e >= EE) return;
    int s = src[e], d = dst[e];
    float4 a = X4[s * 8 + sub];
    float4 b = X4[d * 8 + sub];
    float p = a.x * b.x + a.y * b.y + a.z * b.z + a.w * b.w;
    p += __shfl_xor_sync(0xffffffffu, p, 1);
    p += __shfl_xor_sync(0xffffffffu, p, 2);
    p += __shfl_xor_sync(0xffffffffu, p, 4);
    if (sub == 0) g_cos[e] = p * g_rn[s] * g_rn[d];
}

__global__ void k_sel_init() {
    int t = threadIdx.x;
    if (t < 256) g_hist[t] = 0;
    if (t == 0) { g_prefix = 0u; g_kremain = CUT_K; g_ticket = 0u; }
}

__global__ void k_hist(int pass, int shift) {
    __shared__ unsigned sh[256];
    int t = threadIdx.x;
    sh[t] = 0;
    __syncthreads();
    unsigned pref = g_prefix;
    int stride = gridDim.x * blockDim.x;
    for (int i = blockIdx.x * blockDim.x + t; i < EE; i += stride) {
        unsigned u = fkey(g_cos[i]);
        if (pass == 0 || ((u ^ pref) >> (shift + 8)) == 0)
            atomicAdd(&sh[(u >> shift) & 255u], 1u);
    }
    __syncthreads();
    if (sh[t]) atomicAdd(&g_hist[t], sh[t]);
}

__global__ void k_scan(int shift) {
    __shared__ unsigned s[256];
    int t = threadIdx.x;
    unsigned c = g_hist[t];
    s[t] = c;
    __syncthreads();
    // Hillis-Steele inclusive scan
    for (int off = 1; off < 256; off <<= 1) {
        unsigned v = (t >= off) ? s[t - off] : 0u;
        __syncthreads();
        s[t] += v;
        __syncthreads();
    }
    unsigned incl = s[t];
    unsigned excl = incl - c;
    unsigned kr = g_kremain;
    __syncthreads();
    if (incl >= kr && excl < kr) {
        g_prefix |= ((unsigned)t) << shift;
        g_kremain = kr - excl;
    }
    g_hist[t] = 0;
}

// 8 lanes per edge: message scatter with pruning. SQ=0 -> scale norm[src], SQ=1 -> norm[src]^2
template <int SQ>
__global__ void k_scatter(const float4* __restrict__ X4, float* __restrict__ Y,
                          const int* __restrict__ src, const int* __restrict__ dst) {
    int gid = blockIdx.x * blockDim.x + threadIdx.x;
    int e   = gid >> 3;
    int sub = gid & 7;
    int lane = threadIdx.x & 31;
    int leader = lane & 24;  // first lane of this 8-lane group
    bool valid = (e < EE);

    int keep = 0;
    if (valid && sub == 0) {
        unsigned T = g_prefix;
        unsigned need_eq = g_kremain;
        unsigned u = fkey(g_cos[e]);
        if (u > T) keep = 1;
        else if (u == T) {
            unsigned tk = atomicAdd(&g_ticket, 1u);
            keep = (tk >= need_eq) ? 1 : 0;
        }
    }
    keep = __shfl_sync(0xffffffffu, keep, leader);
    if (!valid || !keep) return;

    int s = src[e], d = dst[e];
    float ns = g_norm[s];
    if (SQ) ns *= ns;
    float4 a = X4[s * 8 + sub];
    a.x *= ns; a.y *= ns; a.z *= ns; a.w *= ns;
    float* p = Y + d * DD + sub * 4;
    asm volatile("red.global.add.v4.f32 [%0], {%1, %2, %3, %4};"
                 :: "l"(p), "f"(a.x), "f"(a.y), "f"(a.z), "f"(a.w)
                 : "memory");
}

// out[i,:] = (Y2[i,:] * norm[i]) @ W^T      W is [32,32] row-major (W[o*32+k])
__global__ void k_fc(const float4* __restrict__ Y4, const float* __restrict__ W,
                     float* __restrict__ out) {
    __shared__ float sW[DD * DD];
    int t = threadIdx.x;
    // 256 threads load 1024 floats
    #pragma unroll
    for (int i = 0; i < 4; i++) sW[t + i * 256] = W[t + i * 256];
    __syncthreads();

    int node = blockIdx.x * blockDim.x + t;
    if (node >= NN) return;
    float nrm = g_norm[node];
    float y[DD];
    #pragma unroll
    for (int j = 0; j < 8; j++) {
        float4 v = Y4[node * 8 + j];
        y[j * 4 + 0] = v.x * nrm;
        y[j * 4 + 1] = v.y * nrm;
        y[j * 4 + 2] = v.z * nrm;
        y[j * 4 + 3] = v.w * nrm;
    }
    #pragma unroll
    for (int o = 0; o < DD; o += 4) {
        float4 acc = make_float4(0.f, 0.f, 0.f, 0.f);
        #pragma unroll
        for (int k = 0; k < DD; k++) {
            float yk = y[k];
            acc.x += yk * sW[(o + 0) * DD + k];
            acc.y += yk * sW[(o + 1) * DD + k];
            acc.z += yk * sW[(o + 2) * DD + k];
            acc.w += yk * sW[(o + 3) * DD + k];
        }
        *reinterpret_cast<float4*>(out + node * DD + o) = acc;
    }
}

// ---------------- launch ----------------

static void run_select() {
    for (int pass = 0; pass < 4; pass++) {
        int shift = 24 - 8 * pass;
        k_hist<<<1184, 256>>>(pass, shift);
        k_scan<<<1, 256>>>(shift);
    }
}

extern "C" void kernel_launch(void* const* d_in, const int* in_sizes, int n_in,
                              void* d_out, int out_size) {
    const float* F   = (const float*)d_in[0];
    const float* W   = (const float*)d_in[1];
    const int*   src = (const int*)d_in[2];
    const int*   dst = (const int*)d_in[3];
    float* out = (float*)d_out;

    const float4* F4 = (const float4*)F;

    float* Y1; float* Y2;
    // device-symbol addresses via kernels only: use the globals directly through
    // small helper kernels. For memset-style zeroing we need raw pointers; fetch
    // them with cudaGetSymbolAddress (not an allocation, not a stream op).
    void* p1; void* p2;
    cudaGetSymbolAddress(&p1, g_Y1);
    cudaGetSymbolAddress(&p2, g_Y2);
    Y1 = (float*)p1; Y2 = (float*)p2;

    const int TB = 256;
    const int gridN   = (NN + TB - 1) / TB;          // 391
    const int gridE   = (EE + TB - 1) / TB;          // 6250
    const int gridN8  = (NN * 8) / TB;               // 3125 (exact)
    const int gridE8  = (EE * 8) / TB;               // 50000 (exact)

    // degree + symmetric norm (static across hops)
    k_zero_deg<<<gridN, TB>>>();
    k_deg<<<gridE, TB>>>(dst);
    k_norm<<<gridN, TB>>>();

    // ---- hop 1: input F ----
    k_rn<<<gridN8, TB>>>(F4);
    k_cos<<<gridE8, TB>>>(F4, src, dst);
    k_sel_init<<<1, 256>>>();
    run_select();
    k_zeroY<<<gridN8, TB>>>((float4*)Y1);
    k_scatter<0><<<gridE8, TB>>>(F4, Y1, src, dst);

    // ---- hop 2: input Y1 (cosine is scale-invariant; norm folded as norm^2) ----
    k_rn<<<gridN8, TB>>>((const float4*)Y1);
    k_cos<<<gridE8, TB>>>((const float4*)Y1, src, dst);
    k_sel_init<<<1, 256>>>();
    run_select();
    k_zeroY<<<gridN8, TB>>>((float4*)Y2);
    k_scatter<1><<<gridE8, TB>>>((const float4*)Y1, Y2, src, dst);

    // ---- final: out = (Y2 * norm) @ W^T ----
    k_fc<<<gridN, TB>>>((const float4*)Y2, W, out);
}

// round 3
// speedup vs baseline: 1.1728x; 1.1728x over previous
#include <cuda_runtime.h>
#include <cstdint>

#define NN 100000
#define EE 1600000
#define EH 800000          // EE/2 (unroll-2 split)
#define DD 32
#define CUT_K 320000       // int(1600000 * 0.2)
#define EPS 1e-12f

// ---------------- scratch (static device globals; no allocation) ----------------
__device__ float     g_Y1[NN * DD];
__device__ float     g_Y2[NN * DD];
__device__ unsigned  g_key[EE];     // monotone uint key of cosine
__device__ float     g_rn[NN];      // 1 / max(||row||, eps)
__device__ float     g_norm[NN];    // clip(deg,1)^-0.5
__device__ int       g_deg[NN];
__device__ unsigned  g_hist[256];
__device__ unsigned  g_prefix;      // radix-select prefix / final threshold key
__device__ unsigned  g_kremain;     // final = #equal-to-threshold keys to drop
__device__ unsigned  g_ticket;      // tie-break ticket counter

// monotone float -> uint key (ascending float order == ascending unsigned order)
__device__ __forceinline__ unsigned fkey(float f) {
    unsigned u = __float_as_uint(f);
    return (u & 0x80000000u) ? ~u : (u | 0x80000000u);
}

// ---------------- kernels ----------------

// zero deg + hist + selector scalars in one pass
__global__ void k_init() {
    int i = blockIdx.x * blockDim.x + threadIdx.x;
    if (i < NN) g_deg[i] = 0;
    if (i < 256) g_hist[i] = 0;
    if (i == 0) { g_prefix = 0u; g_kremain = CUT_K; g_ticket = 0u; }
}

__global__ void k_deg(const int* __restrict__ dst) {
    int e = blockIdx.x * blockDim.x + threadIdx.x;
    if (e < EE) atomicAdd(&g_deg[dst[e]], 1);
}

__global__ void k_norm() {
    int i = blockIdx.x * blockDim.x + threadIdx.x;
    if (i < NN) {
        int d = g_deg[i];
        if (d < 1) d = 1;
        g_norm[i] = 1.0f / sqrtf((float)d);
    }
}

// zero Y; optionally re-arm the radix selector for the next hop
__global__ void k_zeroY(float4* __restrict__ Y4, int reset) {
    int i = blockIdx.x * blockDim.x + threadIdx.x;
    if (i < NN * (DD / 4)) Y4[i] = make_float4(0.f, 0.f, 0.f, 0.f);
    if (reset && i == 0) { g_prefix = 0u; g_kremain = CUT_K; g_ticket = 0u; }
}

// 8 lanes per node: inverse L2 norm of each row
__global__ void k_rn(const float4* __restrict__ X4) {
    int gid  = blockIdx.x * blockDim.x + threadIdx.x;
    int node = gid >> 3;
    int sub  = gid & 7;
    if (node >= NN) return;
    float4 v = X4[node * 8 + sub];
    float s = v.x * v.x + v.y * v.y + v.z * v.z + v.w * v.w;
    s += __shfl_xor_sync(0xffffffffu, s, 1);
    s += __shfl_xor_sync(0xffffffffu, s, 2);
    s += __shfl_xor_sync(0xffffffffu, s, 4);
    if (sub == 0) g_rn[node] = 1.0f / fmaxf(sqrtf(s), EPS);
}

// 8 lanes per edge, 2 edges per thread-group; writes keys + fused radix pass-0 hist
__global__ void k_cos(const float4* __restrict__ X4,
                      const int* __restrict__ src, const int* __restrict__ dst) {
    __shared__ unsigned sh[256];
    sh[threadIdx.x] = 0;   // blockDim == 256
    __syncthreads();

    int gid = blockIdx.x * blockDim.x + threadIdx.x;
    int e0  = gid >> 3;
    int sub = gid & 7;
    int e1  = e0 + EH;

    int s0 = src[e0], d0 = dst[e0];
    int s1 = src[e1], d1 = dst[e1];
    float4 a0 = X4[s0 * 8 + sub];
    float4 b0 = X4[d0 * 8 + sub];
    float4 a1 = X4[s1 * 8 + sub];
    float4 b1 = X4[d1 * 8 + sub];

    float p0 = a0.x * b0.x + a0.y * b0.y + a0.z * b0.z + a0.w * b0.w;
    float p1 = a1.x * b1.x + a1.y * b1.y + a1.z * b1.z + a1.w * b1.w;
    #pragma unroll
    for (int off = 1; off < 8; off <<= 1) {
        p0 += __shfl_xor_sync(0xffffffffu, p0, off);
        p1 += __shfl_xor_sync(0xffffffffu, p1, off);
    }
    if (sub == 0) {
        unsigned k0 = fkey(p0 * g_rn[s0] * g_rn[d0]);
        unsigned k1 = fkey(p1 * g_rn[s1] * g_rn[d1]);
        g_key[e0] = k0;
        g_key[e1] = k1;
        atomicAdd(&sh[k0 >> 24], 1u);
        atomicAdd(&sh[k1 >> 24], 1u);
    }
    __syncthreads();
    unsigned c = sh[threadIdx.x];
    if (c) atomicAdd(&g_hist[threadIdx.x], c);
}

// radix-select histogram for passes 1..3 (keys already materialized)
__global__ void k_hist(int shift) {
    __shared__ unsigned sh[256];
    int t = threadIdx.x;
    sh[t] = 0;
    __syncthreads();
    unsigned pref = g_prefix;
    int stride = gridDim.x * blockDim.x;
    for (int i = blockIdx.x * blockDim.x + t; i < EE; i += stride) {
        unsigned u = g_key[i];
        if (((u ^ pref) >> (shift + 8)) == 0)
            atomicAdd(&sh[(u >> shift) & 255u], 1u);
    }
    __syncthreads();
    if (sh[t]) atomicAdd(&g_hist[t], sh[t]);
}

__global__ void k_scan(int shift) {
    __shared__ unsigned s[256];
    int t = threadIdx.x;
    unsigned c = g_hist[t];
    s[t] = c;
    __syncthreads();
    for (int off = 1; off < 256; off <<= 1) {
        unsigned v = (t >= off) ? s[t - off] : 0u;
        __syncthreads();
        s[t] += v;
        __syncthreads();
    }
    unsigned incl = s[t];
    unsigned excl = incl - c;
    unsigned kr = g_kremain;
    __syncthreads();
    if (incl >= kr && excl < kr) {
        g_prefix |= ((unsigned)t) << shift;
        g_kremain = kr - excl;
    }
    g_hist[t] = 0;
}

// 8 lanes per edge, 2 edges per group: pruned message scatter via red.v4
// SQ=0 -> scale norm[src], SQ=1 -> norm[src]^2
template <int SQ>
__global__ void k_scatter(const float4* __restrict__ X4, float* __restrict__ Y,
                          const int* __restrict__ src, const int* __restrict__ dst) {
    int gid = blockIdx.x * blockDim.x + threadIdx.x;
    int e0  = gid >> 3;
    int sub = gid & 7;
    int e1  = e0 + EH;
    int lane   = threadIdx.x & 31;
    int leader = lane & 24;

    unsigned kp = 0;
    if (sub == 0) {
        unsigned T = g_prefix;
        unsigned need_eq = g_kremain;
        unsigned u0 = g_key[e0];
        unsigned u1 = g_key[e1];
        if (u0 > T) kp |= 1u;
        else if (u0 == T && atomicAdd(&g_ticket, 1u) >= need_eq) kp |= 1u;
        if (u1 > T) kp |= 2u;
        else if (u1 == T && atomicAdd(&g_ticket, 1u) >= need_eq) kp |= 2u;
    }
    kp = __shfl_sync(0xffffffffu, kp, leader);
    if (kp == 0) return;

    float4 a0, a1;
    int d0 = 0, d1 = 0;
    if (kp & 1u) {
        int s = src[e0]; d0 = dst[e0];
        float ns = g_norm[s]; if (SQ) ns *= ns;
        a0 = X4[s * 8 + sub];
        a0.x *= ns; a0.y *= ns; a0.z *= ns; a0.w *= ns;
    }
    if (kp & 2u) {
        int s = src[e1]; d1 = dst[e1];
        float ns = g_norm[s]; if (SQ) ns *= ns;
        a1 = X4[s * 8 + sub];
        a1.x *= ns; a1.y *= ns; a1.z *= ns; a1.w *= ns;
    }
    if (kp & 1u) {
        float* p = Y + d0 * DD + sub * 4;
        asm volatile("red.global.add.v4.f32 [%0], {%1, %2, %3, %4};"
                     :: "l"(p), "f"(a0.x), "f"(a0.y), "f"(a0.z), "f"(a0.w) : "memory");
    }
    if (kp & 2u) {
        float* p = Y + d1 * DD + sub * 4;
        asm volatile("red.global.add.v4.f32 [%0], {%1, %2, %3, %4};"
                     :: "l"(p), "f"(a1.x), "f"(a1.y), "f"(a1.z), "f"(a1.w) : "memory");
    }
}

// out[i,:] = (Y2[i,:] * norm[i]) @ W^T    W is [32,32] row-major
__global__ void k_fc(const float4* __restrict__ Y4, const float* __restrict__ W,
                     float* __restrict__ out) {
    __shared__ float sW[DD * DD];
    int t = threadIdx.x;
    #pragma unroll
    for (int i = 0; i < 4; i++) sW[t + i * 256] = W[t + i * 256];
    __syncthreads();

    int node = blockIdx.x * blockDim.x + t;
    if (node >= NN) return;
    float nrm = g_norm[node];
    float y[DD];
    #pragma unroll
    for (int j = 0; j < 8; j++) {
        float4 v = Y4[node * 8 + j];
        y[j * 4 + 0] = v.x * nrm;
        y[j * 4 + 1] = v.y * nrm;
        y[j * 4 + 2] = v.z * nrm;
        y[j * 4 + 3] = v.w * nrm;
    }
    #pragma unroll
    for (int o = 0; o < DD; o += 4) {
        float4 acc = make_float4(0.f, 0.f, 0.f, 0.f);
        #pragma unroll
        for (int k = 0; k < DD; k++) {
            float yk = y[k];
            acc.x += yk * sW[(o + 0) * DD + k];
            acc.y += yk * sW[(o + 1) * DD + k];
            acc.z += yk * sW[(o + 2) * DD + k];
            acc.w += yk * sW[(o + 3) * DD + k];
        }
        *reinterpret_cast<float4*>(out + node * DD + o) = acc;
    }
}

// ---------------- launch ----------------

extern "C" void kernel_launch(void* const* d_in, const int* in_sizes, int n_in,
                              void* d_out, int out_size) {
    const float* F   = (const float*)d_in[0];
    const float* W   = (const float*)d_in[1];
    const int*   src = (const int*)d_in[2];
    const int*   dst = (const int*)d_in[3];
    float* out = (float*)d_out;

    const float4* F4 = (const float4*)F;

    void* p1; void* p2;
    cudaGetSymbolAddress(&p1, g_Y1);
    cudaGetSymbolAddress(&p2, g_Y2);
    float* Y1 = (float*)p1;
    float* Y2 = (float*)p2;

    const int TB = 256;
    const int gridN  = (NN + TB - 1) / TB;   // 391
    const int gridE  = (EE + TB - 1) / TB;   // 6250
    const int gridN8 = (NN * 8) / TB;        // 3125 (exact)
    const int gridE2 = (EH * 8) / TB;        // 25000 (exact, 2 edges/group)

    // degree + symmetric norm + selector init
    k_init<<<gridN, TB>>>();
    k_deg<<<gridE, TB>>>(dst);
    k_norm<<<gridN, TB>>>();

    // ---- hop 1 ----
    k_rn<<<gridN8, TB>>>(F4);
    k_cos<<<gridE2, TB>>>(F4, src, dst);           // fused radix pass-0
    k_scan<<<1, 256>>>(24);
    for (int shift = 16; shift >= 0; shift -= 8) {
        k_hist<<<1184, 256>>>(shift);
        k_scan<<<1, 256>>>(shift);
    }
    k_zeroY<<<gridN8, TB>>>((float4*)Y1, 0);
    k_scatter<0><<<gridE2, TB>>>(F4, Y1, src, dst);

    // ---- hop 2 (cosine scale-invariant; norm folded as norm^2) ----
    k_zeroY<<<gridN8, TB>>>((float4*)Y2, 1);       // also re-arms selector
    k_rn<<<gridN8, TB>>>((const float4*)Y1);
    k_cos<<<gridE2, TB>>>((const float4*)Y1, src, dst);
    k_scan<<<1, 256>>>(24);
    for (int shift = 16; shift >= 0; shift -= 8) {
        k_hist<<<1184, 256>>>(shift);
        k_scan<<<1, 256>>>(shift);
    }
    k_scatter<1><<<gridE2, TB>>>((const float4*)Y1, Y2, src, dst);

    // ---- final: out = (Y2 * norm) @ W^T ----
    k_fc<<<gridN, TB>>>((const float4*)Y2, W, out);
}